// round 14
// baseline (speedup 1.0000x reference)
#include <cuda_runtime.h>
#include <cuda_fp16.h>
#include <math.h>
#include <stdint.h>

// Problem constants
#define T_   2048
#define E_   16
#define H_   2048
#define I_   1408
#define K_   4
#define A_TOT (T_ * K_)   // 8192 assignments

// GEMM tiling: CTA 128x128, 4 warps (warp 64x64), fp16 m16n8k16 + ldmatrix
// A: fp16 cp.async 3-stage; B: fp32 LDG.cg (L1-bypass) -> cvt -> fp16 smem x2
#define BM 128
#define BN 128
#define BK 64                          // K elements per tile
#define NTHR 128
#define A_STAGE 16384                  // 128 rows x 128 B
#define A3 (3 * A_STAGE)               // 49152
#define BBUF 16384
#define GEMM_SMEM (A3 + 2 * BBUF)      // 81920

// ---------------- Device scratch ----------------
__device__ float  d_topk_w[A_TOT];
__device__ int    d_tok[A_TOT];
__device__ float  d_wt[A_TOT];
__device__ int    d_pos[A_TOT];
__device__ int    d_off[E_ + 1];
__device__ __half d_xs16[(size_t)A_TOT * H_];   // gathered x, fp16
__device__ __half d_h16[(size_t)A_TOT * I_];    // silu(g)*u fp16
__device__ float  d_obuf[(size_t)A_TOT * H_];   // weighted down outputs fp32

// ---------------- helpers ----------------
__device__ __forceinline__ uint32_t smem_u32(const void* p) {
    uint32_t a;
    asm("{ .reg .u64 t; cvta.to.shared.u64 t, %1; cvt.u32.u64 %0, t; }" : "=r"(a) : "l"(p));
    return a;
}
__device__ __forceinline__ uint32_t pack_f2h(float a, float b) {
    uint32_t r;
    asm("{ .reg .f16 lo, hi;\n\t"
        "cvt.rn.f16.f32 lo, %1;\n\t"
        "cvt.rn.f16.f32 hi, %2;\n\t"
        "mov.b32 %0, {lo, hi}; }"
        : "=r"(r) : "f"(a), "f"(b));
    return r;
}

#define MMA_F16(c, a, b) \
    asm volatile("mma.sync.aligned.m16n8k16.row.col.f32.f16.f16.f32 " \
        "{%0,%1,%2,%3}, {%4,%5,%6,%7}, {%8,%9}, {%0,%1,%2,%3};" \
        : "+f"((c)[0]), "+f"((c)[1]), "+f"((c)[2]), "+f"((c)[3]) \
        : "r"((a)[0]), "r"((a)[1]), "r"((a)[2]), "r"((a)[3]), "r"((b)[0]), "r"((b)[1]))

#define LDSM_X4(r0, r1, r2, r3, addr) \
    asm volatile("ldmatrix.sync.aligned.m8n8.x4.shared.b16 {%0,%1,%2,%3}, [%4];" \
        : "=r"(r0), "=r"(r1), "=r"(r2), "=r"(r3) : "r"(addr))

// ---------------- 1. Router + deterministic counting sort (one CTA) ----------------
__global__ void router_sort(const float* __restrict__ logits) {
    __shared__ int sidx[A_TOT];   // 32 KB
    __shared__ int scnt[256];
    __shared__ int sbase[256];
    int tid = threadIdx.x;

    for (int t = tid; t < T_; t += 256) {
        float l[E_];
#pragma unroll
        for (int e = 0; e < E_; e++) l[e] = logits[t * E_ + e];
        unsigned used = 0u;
        float val[K_]; int idx[K_];
#pragma unroll
        for (int k = 0; k < K_; k++) {
            float bv = -INFINITY; int bi = 0;
#pragma unroll
            for (int e = 0; e < E_; e++) {
                bool ok = !((used >> e) & 1u) && (l[e] > bv);
                bv = ok ? l[e] : bv;
                bi = ok ? e : bi;
            }
            used |= (1u << bi);
            val[k] = bv; idx[k] = bi;
        }
        float m = val[0], s = 0.f;
#pragma unroll
        for (int k = 0; k < K_; k++) { val[k] = __expf(val[k] - m); s += val[k]; }
        float inv = 1.f / s;
#pragma unroll
        for (int k = 0; k < K_; k++) {
            sidx[t * K_ + k] = idx[k];
            d_topk_w[t * K_ + k] = val[k] * inv;
        }
    }
    __syncthreads();

    const int CH = A_TOT / 16;
    int e = tid >> 4, c = tid & 15, cn = 0;
    for (int a = c * CH; a < (c + 1) * CH; a++) cn += (sidx[a] == e);
    scnt[tid] = cn;
    __syncthreads();
    if (tid == 0) {
        int run = 0;
        for (int ee = 0; ee < E_; ee++) {
            d_off[ee] = run;
            for (int cc = 0; cc < 16; cc++) { sbase[ee * 16 + cc] = run; run += scnt[ee * 16 + cc]; }
        }
        d_off[E_] = run;
    }
    __syncthreads();
    int p = sbase[tid];
    for (int a = c * CH; a < (c + 1) * CH; a++) {
        if (sidx[a] == e) {
            d_tok[p] = a >> 2;
            d_wt[p]  = d_topk_w[a];
            d_pos[a] = p;
            p++;
        }
    }
}

// ---------------- 2. Gather x rows -> fp16 ----------------
__global__ void gather_kernel(const float* __restrict__ x) {
    int p = blockIdx.x;
    int tok = d_tok[p];
    const float4* src = (const float4*)(x + (size_t)tok * H_);
    uint32_t* dst = (uint32_t*)(d_xs16 + (size_t)p * H_);
    for (int i = threadIdx.x; i < H_ / 4; i += 256) {
        float4 v = src[i];
        dst[2 * i]     = pack_f2h(v.x, v.y);
        dst[2 * i + 1] = pack_f2h(v.z, v.w);
    }
}

// ---------------- 3. Grouped GEMM (fp16 mma + in-flight fp32->fp16 B convert) ----------------
// MODE 1: B rows interleave gate(B0)/up(B1) features -> d_h16 = f16(silu(g)*u)
// MODE 2: B = down(B0) -> d_obuf = wt * (A*B^T)  (fp32)
#define ISSUE_A(kt, st) do {                                                      \
    if ((kt) < NT) {                                                              \
        uint32_t sa = smbase + (st) * A_STAGE + aoff0;                            \
        const __half* srca = Abase + (size_t)(kt) * BK;                           \
        _Pragma("unroll")                                                         \
        for (int i = 0; i < 8; i++) {                                             \
            asm volatile("cp.async.cg.shared.global [%0], [%1], 16, %2;"          \
                         :: "r"(sa + i * 2048u), "l"(srca + (size_t)i * astride), \
                            "r"(apred[i]) : "memory");                            \
        }                                                                         \
    }                                                                             \
    asm volatile("cp.async.commit_group;" ::: "memory");                          \
} while (0)

// B loads bypass L1 (ld.global.cg): streamed once per CTA, reuse lives in L2.
#define LDG_B(kt) do {                                                            \
    const float* bsrc = Bbase + (size_t)(kt) * BK;                                \
    _Pragma("unroll")                                                             \
    for (int i = 0; i < 8; i++) {                                                 \
        br[2 * i]     = __ldcg((const float4*)(bsrc + (size_t)i * bstride));      \
        br[2 * i + 1] = __ldcg((const float4*)(bsrc + (size_t)i * bstride + 4));  \
    }                                                                             \
} while (0)

#define CVT_STS_B(buf) do {                                                       \
    uint32_t bs = smbase + A3 + (uint32_t)(buf) * BBUF + boff0;                   \
    _Pragma("unroll")                                                             \
    for (int i = 0; i < 8; i++) {                                                 \
        uint4 o;                                                                  \
        o.x = pack_f2h(br[2 * i].x,     br[2 * i].y);                             \
        o.y = pack_f2h(br[2 * i].z,     br[2 * i].w);                             \
        o.z = pack_f2h(br[2 * i + 1].x, br[2 * i + 1].y);                         \
        o.w = pack_f2h(br[2 * i + 1].z, br[2 * i + 1].w);                         \
        asm volatile("st.shared.v4.b32 [%0], {%1,%2,%3,%4};"                      \
                     :: "r"(bs + i * 2048u), "r"(o.x), "r"(o.y), "r"(o.z),        \
                        "r"(o.w) : "memory");                                     \
    }                                                                             \
} while (0)

template <int KDIM, int MODE>
__global__ __launch_bounds__(NTHR, 2)
void gemm_tc(const __half* __restrict__ A, const float* __restrict__ B0,
             const float* __restrict__ B1) {
    constexpr int NT = KDIM / BK;
    int e = blockIdx.z;
    int base = d_off[e];
    int n_e  = d_off[e + 1] - base;
    int m0 = blockIdx.y * BM;
    if (m0 >= n_e) return;
    int n0 = blockIdx.x * BN;

    extern __shared__ char sm[];
    uint32_t smbase = smem_u32(sm);
    int tid = threadIdx.x;
    int wid = tid >> 5, lane = tid & 31;
    int q = lane >> 2, tig = lane & 3;
    int rr = tid >> 3, jc = tid & 7;     // loader: base row (0..15), 8-elem chunk

    // ---- A loader state (rows rr+16i) ----
    uint32_t aoff0 = (uint32_t)(rr * 128 + ((jc ^ (rr & 7)) << 4));
    int ra0 = base + m0 + rr;
    if (ra0 > A_TOT - 1) ra0 = A_TOT - 1;
    const __half* Abase = A + (size_t)ra0 * KDIM + jc * 8;
    const size_t astride = (size_t)16 * KDIM;
    int apred[8];
#pragma unroll
    for (int i = 0; i < 8; i++) {
        int r = m0 + rr + 16 * i;
        apred[i] = (r < n_e) ? 16 : 0;
    }

    // ---- B loader state ----
    const float* Bbase;
    size_t bstride;
    if (MODE == 1) {
        int f = (n0 >> 1) + (rr >> 1);
        const float* srcw = (rr & 1) ? B1 : B0;
        Bbase = srcw + ((size_t)e * I_ + f) * KDIM + jc * 8;
        bstride = (size_t)8 * KDIM;
    } else {
        Bbase = B0 + ((size_t)e * H_ + n0 + rr) * KDIM + jc * 8;
        bstride = (size_t)16 * KDIM;
    }
    uint32_t boff0 = aoff0;

    float4 br[16];

    // prologue
    ISSUE_A(0, 0);
    ISSUE_A(1, 1);
    LDG_B(0);
    CVT_STS_B(0);
    __syncthreads();

    int wm = (wid & 1) << 6;    // warp M band: 0/64
    int wn = (wid >> 1) << 6;   // warp N band: 0/64

    // ldmatrix per-thread geometry
    int c7 = lane & 7;
    int subA_m = (lane >> 3) & 1;
    int subA_k = (lane >> 4) & 1;
    int subB_k = (lane >> 3) & 1;
    int subB_n = (lane >> 4) & 1;
    uint32_t rowbaseA[4], rowbaseB[4];
#pragma unroll
    for (int mt = 0; mt < 4; mt++)
        rowbaseA[mt] = (uint32_t)((wm + mt * 16 + subA_m * 8 + c7) * 128);
#pragma unroll
    for (int p = 0; p < 4; p++)
        rowbaseB[p] = (uint32_t)((wn + p * 16 + subB_n * 8 + c7) * 128);

    float acc[4][8][4];
#pragma unroll
    for (int mt = 0; mt < 4; mt++)
#pragma unroll
        for (int nt = 0; nt < 8; nt++)
#pragma unroll
            for (int r = 0; r < 4; r++) acc[mt][nt][r] = 0.f;

    for (int kt = 0; kt < NT; kt++) {
        if (kt + 1 < NT) LDG_B(kt + 1);
        ISSUE_A(kt + 2, (kt + 2) % 3);
        asm volatile("cp.async.wait_group 1;" ::: "memory");

        uint32_t stgA = smbase + (kt % 3) * A_STAGE;
        uint32_t stgB = smbase + A3 + (uint32_t)(kt & 1) * BBUF;
#pragma unroll
        for (int kk = 0; kk < 4; kk++) {
            uint32_t offA = (uint32_t)(((2 * kk + subA_k) ^ c7) << 4);
            uint32_t offB = (uint32_t)(((2 * kk + subB_k) ^ c7) << 4);
            uint32_t a[4][4];
#pragma unroll
            for (int mt = 0; mt < 4; mt++)
                LDSM_X4(a[mt][0], a[mt][1], a[mt][2], a[mt][3],
                        stgA + rowbaseA[mt] + offA);
            uint32_t b[8][2];
#pragma unroll
            for (int p = 0; p < 4; p++)
                LDSM_X4(b[2 * p][0], b[2 * p][1], b[2 * p + 1][0], b[2 * p + 1][1],
                        stgB + rowbaseB[p] + offB);
#pragma unroll
            for (int mt = 0; mt < 4; mt++)
#pragma unroll
                for (int nt = 0; nt < 8; nt++)
                    MMA_F16(acc[mt][nt], a[mt], b[nt]);
        }
        if (kt + 1 < NT) CVT_STS_B((kt + 1) & 1);
        __syncthreads();
    }

    // epilogue
#pragma unroll
    for (int mt = 0; mt < 4; mt++) {
        int m  = m0 + wm + mt * 16 + q;
        int m8 = m + 8;
        if (MODE == 1) {
#pragma unroll
            for (int nt = 0; nt < 8; nt++) {
                int f = (n0 + wn + nt * 8) / 2 + tig;
                if (m < n_e) {
                    float g = acc[mt][nt][0], u = acc[mt][nt][1];
                    float h = g * (1.f / (1.f + __expf(-g))) * u;
                    d_h16[(size_t)(base + m) * I_ + f] = __float2half_rn(h);
                }
                if (m8 < n_e) {
                    float g = acc[mt][nt][2], u = acc[mt][nt][3];
                    float h = g * (1.f / (1.f + __expf(-g))) * u;
                    d_h16[(size_t)(base + m8) * I_ + f] = __float2half_rn(h);
                }
            }
        } else {
            float w0 = (m  < n_e) ? d_wt[base + m]  : 0.f;
            float w1 = (m8 < n_e) ? d_wt[base + m8] : 0.f;
#pragma unroll
            for (int nt = 0; nt < 8; nt++) {
                int n = n0 + wn + nt * 8 + 2 * tig;
                if (m < n_e)
                    *(float2*)&d_obuf[(size_t)(base + m) * H_ + n] =
                        make_float2(acc[mt][nt][0] * w0, acc[mt][nt][1] * w0);
                if (m8 < n_e)
                    *(float2*)&d_obuf[(size_t)(base + m8) * H_ + n] =
                        make_float2(acc[mt][nt][2] * w1, acc[mt][nt][3] * w1);
            }
        }
    }
}

// ---------------- 4. Combine ----------------
__global__ void combine_kernel(float* __restrict__ out) {
    int gid = blockIdx.x * blockDim.x + threadIdx.x;
    int t = gid / (H_ / 4);
    int h4 = (gid - t * (H_ / 4)) * 4;
    float4 s = make_float4(0.f, 0.f, 0.f, 0.f);
#pragma unroll
    for (int k = 0; k < K_; k++) {
        int p = d_pos[t * K_ + k];
        float4 v = *(const float4*)&d_obuf[(size_t)p * H_ + h4];
        s.x += v.x; s.y += v.y; s.z += v.z; s.w += v.w;
    }
    *(float4*)&out[(size_t)t * H_ + h4] = s;
}

// ---------------- Host ----------------
extern "C" void kernel_launch(void* const* d_in, const int* in_sizes, int n_in,
                              void* d_out, int out_size) {
    const float* x      = (const float*)d_in[0];
    const float* logits = (const float*)d_in[1];
    const float* gate_w = (const float*)d_in[2];
    const float* up_w   = (const float*)d_in[3];
    const float* down_w = (const float*)d_in[4];
    float* out = (float*)d_out;

    static int smem_set = 0;
    if (!smem_set) {
        cudaFuncSetAttribute(gemm_tc<H_, 1>, cudaFuncAttributeMaxDynamicSharedMemorySize, GEMM_SMEM);
        cudaFuncSetAttribute(gemm_tc<I_, 2>, cudaFuncAttributeMaxDynamicSharedMemorySize, GEMM_SMEM);
        smem_set = 1;
    }

    __half *xs_p, *h_p;
    cudaGetSymbolAddress((void**)&xs_p, d_xs16);
    cudaGetSymbolAddress((void**)&h_p,  d_h16);

    router_sort<<<1, 256>>>(logits);
    gather_kernel<<<A_TOT, 256>>>(x);

    dim3 g1(2 * I_ / BN, 8, E_);   // 22 x 8 x 16
    gemm_tc<H_, 1><<<g1, NTHR, GEMM_SMEM>>>(xs_p, gate_w, up_w);

    dim3 g2(H_ / BN, 8, E_);       // 16 x 8 x 16
    gemm_tc<I_, 2><<<g2, NTHR, GEMM_SMEM>>>(h_p, down_w, nullptr);

    combine_kernel<<<(T_ * H_ / 4) / 256, 256>>>(out);
}

// round 15
// speedup vs baseline: 1.1307x; 1.1307x over previous
#include <cuda_runtime.h>
#include <cuda_fp16.h>
#include <math.h>
#include <stdint.h>

// Problem constants
#define T_   2048
#define E_   16
#define H_   2048
#define I_   1408
#define K_   4
#define A_TOT (T_ * K_)   // 8192 assignments

// GEMM tiling: CTA 128x128, 4 warps (warp 64x64), fp16 m16n8k16 + ldmatrix
// A: fp16 cp.async 3-stage; B: fp32 LDG -> reg -> cvt -> fp16 smem double-buffer
// Grid: (Mtiles, Ntiles, E) so co-resident/adjacent CTAs share the SAME B tile in L1/L2.
#define BM 128
#define BN 128
#define BK 64                          // K elements per tile
#define NTHR 128
#define A_STAGE 16384                  // 128 rows x 128 B
#define A3 (3 * A_STAGE)               // 49152
#define BBUF 16384
#define GEMM_SMEM (A3 + 2 * BBUF)      // 81920

// ---------------- Device scratch ----------------
__device__ float  d_topk_w[A_TOT];
__device__ int    d_tok[A_TOT];
__device__ float  d_wt[A_TOT];
__device__ int    d_pos[A_TOT];
__device__ int    d_off[E_ + 1];
__device__ __half d_xs16[(size_t)A_TOT * H_];   // gathered x, fp16
__device__ __half d_h16[(size_t)A_TOT * I_];    // silu(g)*u fp16
__device__ float  d_obuf[(size_t)A_TOT * H_];   // weighted down outputs fp32

// ---------------- helpers ----------------
__device__ __forceinline__ uint32_t smem_u32(const void* p) {
    uint32_t a;
    asm("{ .reg .u64 t; cvta.to.shared.u64 t, %1; cvt.u32.u64 %0, t; }" : "=r"(a) : "l"(p));
    return a;
}
__device__ __forceinline__ uint32_t pack_f2h(float a, float b) {
    uint32_t r;
    asm("{ .reg .f16 lo, hi;\n\t"
        "cvt.rn.f16.f32 lo, %1;\n\t"
        "cvt.rn.f16.f32 hi, %2;\n\t"
        "mov.b32 %0, {lo, hi}; }"
        : "=r"(r) : "f"(a), "f"(b));
    return r;
}

#define MMA_F16(c, a, b) \
    asm volatile("mma.sync.aligned.m16n8k16.row.col.f32.f16.f16.f32 " \
        "{%0,%1,%2,%3}, {%4,%5,%6,%7}, {%8,%9}, {%0,%1,%2,%3};" \
        : "+f"((c)[0]), "+f"((c)[1]), "+f"((c)[2]), "+f"((c)[3]) \
        : "r"((a)[0]), "r"((a)[1]), "r"((a)[2]), "r"((a)[3]), "r"((b)[0]), "r"((b)[1]))

#define LDSM_X4(r0, r1, r2, r3, addr) \
    asm volatile("ldmatrix.sync.aligned.m8n8.x4.shared.b16 {%0,%1,%2,%3}, [%4];" \
        : "=r"(r0), "=r"(r1), "=r"(r2), "=r"(r3) : "r"(addr))

// ---------------- 1. Router + deterministic counting sort (one CTA) ----------------
__global__ void router_sort(const float* __restrict__ logits) {
    __shared__ int sidx[A_TOT];   // 32 KB
    __shared__ int scnt[256];
    __shared__ int sbase[256];
    int tid = threadIdx.x;

    for (int t = tid; t < T_; t += 256) {
        float l[E_];
#pragma unroll
        for (int e = 0; e < E_; e++) l[e] = logits[t * E_ + e];
        unsigned used = 0u;
        float val[K_]; int idx[K_];
#pragma unroll
        for (int k = 0; k < K_; k++) {
            float bv = -INFINITY; int bi = 0;
#pragma unroll
            for (int e = 0; e < E_; e++) {
                bool ok = !((used >> e) & 1u) && (l[e] > bv);
                bv = ok ? l[e] : bv;
                bi = ok ? e : bi;
            }
            used |= (1u << bi);
            val[k] = bv; idx[k] = bi;
        }
        float m = val[0], s = 0.f;
#pragma unroll
        for (int k = 0; k < K_; k++) { val[k] = __expf(val[k] - m); s += val[k]; }
        float inv = 1.f / s;
#pragma unroll
        for (int k = 0; k < K_; k++) {
            sidx[t * K_ + k] = idx[k];
            d_topk_w[t * K_ + k] = val[k] * inv;
        }
    }
    __syncthreads();

    const int CH = A_TOT / 16;
    int e = tid >> 4, c = tid & 15, cn = 0;
    for (int a = c * CH; a < (c + 1) * CH; a++) cn += (sidx[a] == e);
    scnt[tid] = cn;
    __syncthreads();
    if (tid == 0) {
        int run = 0;
        for (int ee = 0; ee < E_; ee++) {
            d_off[ee] = run;
            for (int cc = 0; cc < 16; cc++) { sbase[ee * 16 + cc] = run; run += scnt[ee * 16 + cc]; }
        }
        d_off[E_] = run;
    }
    __syncthreads();
    int p = sbase[tid];
    for (int a = c * CH; a < (c + 1) * CH; a++) {
        if (sidx[a] == e) {
            d_tok[p] = a >> 2;
            d_wt[p]  = d_topk_w[a];
            d_pos[a] = p;
            p++;
        }
    }
}

// ---------------- 2. Gather x rows -> fp16 ----------------
__global__ void gather_kernel(const float* __restrict__ x) {
    int p = blockIdx.x;
    int tok = d_tok[p];
    const float4* src = (const float4*)(x + (size_t)tok * H_);
    uint32_t* dst = (uint32_t*)(d_xs16 + (size_t)p * H_);
    for (int i = threadIdx.x; i < H_ / 4; i += 256) {
        float4 v = src[i];
        dst[2 * i]     = pack_f2h(v.x, v.y);
        dst[2 * i + 1] = pack_f2h(v.z, v.w);
    }
}

// ---------------- 3. Grouped GEMM (fp16 mma + in-flight fp32->fp16 B convert) ----------------
// MODE 1: B rows interleave gate(B0)/up(B1) features -> d_h16 = f16(silu(g)*u)
// MODE 2: B = down(B0) -> d_obuf = wt * (A*B^T)  (fp32)
#define ISSUE_A(kt, st) do {                                                      \
    if ((kt) < NT) {                                                              \
        uint32_t sa = smbase + (st) * A_STAGE + aoff0;                            \
        const __half* srca = Abase + (size_t)(kt) * BK;                           \
        _Pragma("unroll")                                                         \
        for (int i = 0; i < 8; i++) {                                             \
            asm volatile("cp.async.cg.shared.global [%0], [%1], 16, %2;"          \
                         :: "r"(sa + i * 2048u), "l"(srca + (size_t)i * astride), \
                            "r"(apred[i]) : "memory");                            \
        }                                                                         \
    }                                                                             \
    asm volatile("cp.async.commit_group;" ::: "memory");                          \
} while (0)

#define LDG_B(kt) do {                                                            \
    const float* bsrc = Bbase + (size_t)(kt) * BK;                                \
    _Pragma("unroll")                                                             \
    for (int i = 0; i < 8; i++) {                                                 \
        br[2 * i]     = *(const float4*)(bsrc + (size_t)i * bstride);             \
        br[2 * i + 1] = *(const float4*)(bsrc + (size_t)i * bstride + 4);         \
    }                                                                             \
} while (0)

#define CVT_STS_B(buf) do {                                                       \
    uint32_t bs = smbase + A3 + (uint32_t)(buf) * BBUF + boff0;                   \
    _Pragma("unroll")                                                             \
    for (int i = 0; i < 8; i++) {                                                 \
        uint4 o;                                                                  \
        o.x = pack_f2h(br[2 * i].x,     br[2 * i].y);                             \
        o.y = pack_f2h(br[2 * i].z,     br[2 * i].w);                             \
        o.z = pack_f2h(br[2 * i + 1].x, br[2 * i + 1].y);                         \
        o.w = pack_f2h(br[2 * i + 1].z, br[2 * i + 1].w);                         \
        asm volatile("st.shared.v4.b32 [%0], {%1,%2,%3,%4};"                      \
                     :: "r"(bs + i * 2048u), "r"(o.x), "r"(o.y), "r"(o.z),        \
                        "r"(o.w) : "memory");                                     \
    }                                                                             \
} while (0)

template <int KDIM, int MODE>
__global__ __launch_bounds__(NTHR, 2)
void gemm_tc(const __half* __restrict__ A, const float* __restrict__ B0,
             const float* __restrict__ B1) {
    constexpr int NT = KDIM / BK;
    int e = blockIdx.z;
    int base = d_off[e];
    int n_e  = d_off[e + 1] - base;
    int m0 = blockIdx.x * BM;        // M tiles on x: adjacent CTAs share the B tile
    if (m0 >= n_e) return;
    int n0 = blockIdx.y * BN;

    extern __shared__ char sm[];
    uint32_t smbase = smem_u32(sm);
    int tid = threadIdx.x;
    int wid = tid >> 5, lane = tid & 31;
    int q = lane >> 2, tig = lane & 3;
    int rr = tid >> 3, jc = tid & 7;     // loader: base row (0..15), 8-elem chunk

    // ---- A loader state (rows rr+16i) ----
    uint32_t aoff0 = (uint32_t)(rr * 128 + ((jc ^ (rr & 7)) << 4));
    int ra0 = base + m0 + rr;
    if (ra0 > A_TOT - 1) ra0 = A_TOT - 1;
    const __half* Abase = A + (size_t)ra0 * KDIM + jc * 8;
    const size_t astride = (size_t)16 * KDIM;
    int apred[8];
#pragma unroll
    for (int i = 0; i < 8; i++) {
        int r = m0 + rr + 16 * i;
        apred[i] = (r < n_e) ? 16 : 0;
    }

    // ---- B loader state ----
    const float* Bbase;
    size_t bstride;
    if (MODE == 1) {
        int f = (n0 >> 1) + (rr >> 1);
        const float* srcw = (rr & 1) ? B1 : B0;
        Bbase = srcw + ((size_t)e * I_ + f) * KDIM + jc * 8;
        bstride = (size_t)8 * KDIM;
    } else {
        Bbase = B0 + ((size_t)e * H_ + n0 + rr) * KDIM + jc * 8;
        bstride = (size_t)16 * KDIM;
    }
    uint32_t boff0 = aoff0;

    float4 br[16];

    // prologue
    ISSUE_A(0, 0);
    ISSUE_A(1, 1);
    LDG_B(0);
    CVT_STS_B(0);
    __syncthreads();

    int wm = (wid & 1) << 6;    // warp M band: 0/64
    int wn = (wid >> 1) << 6;   // warp N band: 0/64

    // ldmatrix per-thread geometry
    int c7 = lane & 7;
    int subA_m = (lane >> 3) & 1;
    int subA_k = (lane >> 4) & 1;
    int subB_k = (lane >> 3) & 1;
    int subB_n = (lane >> 4) & 1;
    uint32_t rowbaseA[4], rowbaseB[4];
#pragma unroll
    for (int mt = 0; mt < 4; mt++)
        rowbaseA[mt] = (uint32_t)((wm + mt * 16 + subA_m * 8 + c7) * 128);
#pragma unroll
    for (int p = 0; p < 4; p++)
        rowbaseB[p] = (uint32_t)((wn + p * 16 + subB_n * 8 + c7) * 128);

    float acc[4][8][4];
#pragma unroll
    for (int mt = 0; mt < 4; mt++)
#pragma unroll
        for (int nt = 0; nt < 8; nt++)
#pragma unroll
            for (int r = 0; r < 4; r++) acc[mt][nt][r] = 0.f;

    for (int kt = 0; kt < NT; kt++) {
        ISSUE_A(kt + 2, (kt + 2) % 3);
        if (kt + 1 < NT) LDG_B(kt + 1);
        asm volatile("cp.async.wait_group 1;" ::: "memory");

        uint32_t stgA = smbase + (kt % 3) * A_STAGE;
        uint32_t stgB = smbase + A3 + (uint32_t)(kt & 1) * BBUF;
#pragma unroll
        for (int kk = 0; kk < 4; kk++) {
            uint32_t offA = (uint32_t)(((2 * kk + subA_k) ^ c7) << 4);
            uint32_t offB = (uint32_t)(((2 * kk + subB_k) ^ c7) << 4);
            uint32_t a[4][4];
#pragma unroll
            for (int mt = 0; mt < 4; mt++)
                LDSM_X4(a[mt][0], a[mt][1], a[mt][2], a[mt][3],
                        stgA + rowbaseA[mt] + offA);
            uint32_t b[8][2];
#pragma unroll
            for (int p = 0; p < 4; p++)
                LDSM_X4(b[2 * p][0], b[2 * p][1], b[2 * p + 1][0], b[2 * p + 1][1],
                        stgB + rowbaseB[p] + offB);
#pragma unroll
            for (int mt = 0; mt < 4; mt++)
#pragma unroll
                for (int nt = 0; nt < 8; nt++)
                    MMA_F16(acc[mt][nt], a[mt], b[nt]);
        }
        if (kt + 1 < NT) CVT_STS_B((kt + 1) & 1);
        __syncthreads();
    }

    // epilogue
#pragma unroll
    for (int mt = 0; mt < 4; mt++) {
        int m  = m0 + wm + mt * 16 + q;
        int m8 = m + 8;
        if (MODE == 1) {
#pragma unroll
            for (int nt = 0; nt < 8; nt++) {
                int f = (n0 + wn + nt * 8) / 2 + tig;
                if (m < n_e) {
                    float g = acc[mt][nt][0], u = acc[mt][nt][1];
                    float h = g * (1.f / (1.f + __expf(-g))) * u;
                    d_h16[(size_t)(base + m) * I_ + f] = __float2half_rn(h);
                }
                if (m8 < n_e) {
                    float g = acc[mt][nt][2], u = acc[mt][nt][3];
                    float h = g * (1.f / (1.f + __expf(-g))) * u;
                    d_h16[(size_t)(base + m8) * I_ + f] = __float2half_rn(h);
                }
            }
        } else {
            float w0 = (m  < n_e) ? d_wt[base + m]  : 0.f;
            float w1 = (m8 < n_e) ? d_wt[base + m8] : 0.f;
#pragma unroll
            for (int nt = 0; nt < 8; nt++) {
                int n = n0 + wn + nt * 8 + 2 * tig;
                if (m < n_e)
                    *(float2*)&d_obuf[(size_t)(base + m) * H_ + n] =
                        make_float2(acc[mt][nt][0] * w0, acc[mt][nt][1] * w0);
                if (m8 < n_e)
                    *(float2*)&d_obuf[(size_t)(base + m8) * H_ + n] =
                        make_float2(acc[mt][nt][2] * w1, acc[mt][nt][3] * w1);
            }
        }
    }
}

// ---------------- 4. Combine ----------------
__global__ void combine_kernel(float* __restrict__ out) {
    int gid = blockIdx.x * blockDim.x + threadIdx.x;
    int t = gid / (H_ / 4);
    int h4 = (gid - t * (H_ / 4)) * 4;
    float4 s = make_float4(0.f, 0.f, 0.f, 0.f);
#pragma unroll
    for (int k = 0; k < K_; k++) {
        int p = d_pos[t * K_ + k];
        float4 v = *(const float4*)&d_obuf[(size_t)p * H_ + h4];
        s.x += v.x; s.y += v.y; s.z += v.z; s.w += v.w;
    }
    *(float4*)&out[(size_t)t * H_ + h4] = s;
}

// ---------------- Host ----------------
extern "C" void kernel_launch(void* const* d_in, const int* in_sizes, int n_in,
                              void* d_out, int out_size) {
    const float* x      = (const float*)d_in[0];
    const float* logits = (const float*)d_in[1];
    const float* gate_w = (const float*)d_in[2];
    const float* up_w   = (const float*)d_in[3];
    const float* down_w = (const float*)d_in[4];
    float* out = (float*)d_out;

    static int smem_set = 0;
    if (!smem_set) {
        cudaFuncSetAttribute(gemm_tc<H_, 1>, cudaFuncAttributeMaxDynamicSharedMemorySize, GEMM_SMEM);
        cudaFuncSetAttribute(gemm_tc<I_, 2>, cudaFuncAttributeMaxDynamicSharedMemorySize, GEMM_SMEM);
        smem_set = 1;
    }

    __half *xs_p, *h_p;
    cudaGetSymbolAddress((void**)&xs_p, d_xs16);
    cudaGetSymbolAddress((void**)&h_p,  d_h16);

    router_sort<<<1, 256>>>(logits);
    gather_kernel<<<A_TOT, 256>>>(x);

    dim3 g1(8, 2 * I_ / BN, E_);   // 8 x 22 x 16  (x = M tiles)
    gemm_tc<H_, 1><<<g1, NTHR, GEMM_SMEM>>>(xs_p, gate_w, up_w);

    dim3 g2(8, H_ / BN, E_);       // 8 x 16 x 16
    gemm_tc<I_, 2><<<g2, NTHR, GEMM_SMEM>>>(h_p, down_w, nullptr);

    combine_kernel<<<(T_ * H_ / 4) / 256, 256>>>(out);
}